// round 2
// baseline (speedup 1.0000x reference)
#include <cuda_runtime.h>

// out[r, c] = x[r, c] * diag[c], x: 16384 x 2048 f32.
// Streaming column-scale. Each thread handles 4 float4s in the SAME column
// across 4 consecutive rows (addresses 1 row = 512 float4 apart):
//   - 4 independent front-batched LDGs (MLP_p1 = 4)
//   - one diag load reused x4
//   - __ldcs/__stcs: single-touch data, evict-first (no L2 reuse to protect)
// Per-warp accesses stay fully coalesced (32 consecutive float4 = 512B).

#define ROW_F4 512u          // 2048 floats / 4 per row
#define ROWS_PER_THREAD 4

__global__ __launch_bounds__(256) void diag_scale_kernel(
    const float4* __restrict__ x,
    const float4* __restrict__ d,
    float4* __restrict__ out)
{
    unsigned int t = blockIdx.x * 256u + threadIdx.x;   // 0 .. 2097151
    unsigned int col = t & (ROW_F4 - 1u);               // float4 column
    unsigned int rowgrp = t >> 9;                       // group of 4 rows
    unsigned int base = rowgrp * (ROW_F4 * ROWS_PER_THREAD) + col;

    float4 s = __ldg(&d[col]);

    float4 v0 = __ldcs(&x[base]);
    float4 v1 = __ldcs(&x[base + ROW_F4]);
    float4 v2 = __ldcs(&x[base + 2u * ROW_F4]);
    float4 v3 = __ldcs(&x[base + 3u * ROW_F4]);

    v0.x *= s.x; v0.y *= s.y; v0.z *= s.z; v0.w *= s.w;
    v1.x *= s.x; v1.y *= s.y; v1.z *= s.z; v1.w *= s.w;
    v2.x *= s.x; v2.y *= s.y; v2.z *= s.z; v2.w *= s.w;
    v3.x *= s.x; v3.y *= s.y; v3.z *= s.z; v3.w *= s.w;

    __stcs(&out[base],               v0);
    __stcs(&out[base + ROW_F4],      v1);
    __stcs(&out[base + 2u * ROW_F4], v2);
    __stcs(&out[base + 3u * ROW_F4], v3);
}

extern "C" void kernel_launch(void* const* d_in, const int* in_sizes, int n_in,
                              void* d_out, int out_size) {
    const float4* x = (const float4*)d_in[0];
    const float4* d = (const float4*)d_in[1];
    float4* out = (float4*)d_out;

    // 16384*2048/4 = 8,388,608 float4; 4 per thread -> 2,097,152 threads
    const int threads = 256;
    const int blocks = (16384 * 2048 / 4) / (threads * ROWS_PER_THREAD); // 8192

    diag_scale_kernel<<<blocks, threads>>>(x, d, out);
}

// round 3
// speedup vs baseline: 1.0007x; 1.0007x over previous
#include <cuda_runtime.h>
#include <cstdint>

// out[r, c] = x[r, c] * diag[c], x: 16384 x 2048 f32.
// HBM-bound streaming kernel. sm_103a-specific levers:
//   - 256-bit (v8.f32) global loads/stores (Blackwell LDG.256/STG.256):
//     1024B per warp per access, better DRAM burst efficiency.
//   - ld .cs (evict-first, single touch) + st .wt (write-through) so dirty
//     L2 lines don't pile up across back-to-back graph replays.
// Row = 2048 floats = 256 chunks of 8; chunk column = t & 255 (one LOP).
// diag chunk (32B) is reloaded per thread but hits L1/L2 (8KB total vector).

__global__ __launch_bounds__(256) void diag_scale_kernel(
    const float* __restrict__ x,
    const float* __restrict__ d,
    float* __restrict__ out)
{
    unsigned int t = blockIdx.x * 256u + threadIdx.x;     // 0 .. 4,194,303
    unsigned int col8 = (t & 255u) * 8u;                  // float column of chunk
    const float* xp = x + (size_t)t * 8u;
    float*       op = out + (size_t)t * 8u;
    const float* dp = d + col8;

    float v0, v1, v2, v3, v4, v5, v6, v7;
    asm volatile(
        "ld.global.cs.v8.f32 {%0,%1,%2,%3,%4,%5,%6,%7}, [%8];"
        : "=f"(v0), "=f"(v1), "=f"(v2), "=f"(v3),
          "=f"(v4), "=f"(v5), "=f"(v6), "=f"(v7)
        : "l"(xp));

    float s0, s1, s2, s3, s4, s5, s6, s7;
    asm volatile(
        "ld.global.nc.v8.f32 {%0,%1,%2,%3,%4,%5,%6,%7}, [%8];"
        : "=f"(s0), "=f"(s1), "=f"(s2), "=f"(s3),
          "=f"(s4), "=f"(s5), "=f"(s6), "=f"(s7)
        : "l"(dp));

    v0 *= s0; v1 *= s1; v2 *= s2; v3 *= s3;
    v4 *= s4; v5 *= s5; v6 *= s6; v7 *= s7;

    asm volatile(
        "st.global.wt.v8.f32 [%0], {%1,%2,%3,%4,%5,%6,%7,%8};"
        :: "l"(op),
           "f"(v0), "f"(v1), "f"(v2), "f"(v3),
           "f"(v4), "f"(v5), "f"(v6), "f"(v7)
        : "memory");
}

extern "C" void kernel_launch(void* const* d_in, const int* in_sizes, int n_in,
                              void* d_out, int out_size) {
    const float* x = (const float*)d_in[0];
    const float* d = (const float*)d_in[1];
    float* out = (float*)d_out;

    // 16384*2048 floats / 8 per thread = 4,194,304 threads -> 16384 blocks
    const int threads = 256;
    const int blocks = (16384 * 2048 / 8) / threads;  // 16384, exact

    diag_scale_kernel<<<blocks, threads>>>(x, d, out);
}